// round 9
// baseline (speedup 1.0000x reference)
#include <cuda_runtime.h>

// y[b,t,c] = (1/(t+1)) * sum_{j<=t} x[b,j,c]   (cumulative mean along T)
// Two-pass, serialization-free:
//   K1: per-(b, 128-row chunk) channel sums -> g_part   (read 32MB, L2-hot on replay)
//   K2: local register scan + parallel predecessor-partial sum + scaled store
// R6 lesson: k_scanout at 256thr/RPT8 was latency-bound (occ 41%). Go wider:
// 512 threads, 4 rows/thread (16 payload regs) -> ~75% occ; predecessor loop
// split 8 ways and issued after the x-tile LDGs.

#define B_      16
#define T_      8192
#define C_      64
#define CHUNK   128
#define NCHUNK  (T_ / CHUNK)          // 64
#define NBLK    (B_ * NCHUNK)         // 1024
#define CG      16                    // float4 channel groups

// ---- K1 config ----
#define NTHR1   256
#define RL1     (NTHR1 / CG)          // 16
#define RPT1    (CHUNK / RL1)         // 8

// ---- K2 config ----
#define NTHR2   512
#define RL2     (NTHR2 / CG)          // 32 row lanes
#define RPT2    (CHUNK / RL2)         // 4 rows per thread

// Per-chunk channel sums: [b][chunk][c], float4-aligned. 256 KB.
__device__ float4 g_part4[B_ * NCHUNK * CG];

__global__ void __launch_bounds__(NTHR1, 8)
k_partial(const float* __restrict__ x) {
    const int bid = blockIdx.x;
    const int b   = bid >> 6;           // /NCHUNK
    const int ch  = bid & (NCHUNK - 1);
    const int tid = threadIdx.x;
    const int cg  = tid & (CG - 1);
    const int rl  = tid >> 4;

    const int row0 = ch * CHUNK + rl * RPT1;
    const float4* __restrict__ xp =
        (const float4*)(x + ((size_t)(b * T_ + row0)) * C_ + cg * 4);

    float4 s = make_float4(0.f, 0.f, 0.f, 0.f);
    #pragma unroll
    for (int k = 0; k < RPT1; k++) {
        float4 v = xp[k * (C_ / 4)];
        s.x += v.x; s.y += v.y; s.z += v.z; s.w += v.w;
    }

    __shared__ float4 red[RL1][CG];
    red[rl][cg] = s;
    #pragma unroll
    for (int st = RL1 / 2; st > 0; st >>= 1) {
        __syncthreads();
        if (rl < st) {
            float4 o = red[rl + st][cg];
            float4 m = red[rl][cg];
            m.x += o.x; m.y += o.y; m.z += o.z; m.w += o.w;
            red[rl][cg] = m;
        }
    }
    __syncthreads();
    if (rl == 0)
        g_part4[(b * NCHUNK + ch) * CG + cg] = red[0][cg];
}

__global__ void __launch_bounds__(NTHR2, 3)
k_scanout(const float* __restrict__ x, float* __restrict__ y) {
    const int bid = blockIdx.x;
    const int b   = bid >> 6;
    const int ch  = bid & (NCHUNK - 1);
    const int tid = threadIdx.x;
    const int cg  = tid & (CG - 1);
    const int rl  = tid >> 4;           // 0..31

    __shared__ float4 red[RL2][CG];
    __shared__ float  pred[8][C_];
    __shared__ float  predt[C_];
    __shared__ float  s_recip[CHUNK];

    // ---- x tile: issue the 4 independent LDG.128 first ----
    const int row0 = ch * CHUNK + rl * RPT2;
    const size_t off = ((size_t)(b * T_ + row0)) * C_ + cg * 4;
    const float4* __restrict__ xp = (const float4*)(x + off);

    float4 v0 = xp[0 * (C_ / 4)];
    float4 v1 = xp[1 * (C_ / 4)];
    float4 v2 = xp[2 * (C_ / 4)];
    float4 v3 = xp[3 * (C_ / 4)];

    // Reciprocal table for this chunk's global rows (full-precision divide).
    if (tid < CHUNK)
        s_recip[tid] = 1.0f / (float)(ch * CHUNK + tid + 1);

    // Predecessor chunk partials: 8 groups x 64 channels, <=8 loads each (L2-hot),
    // overlapping the in-flight x loads.
    {
        const int c   = tid & (C_ - 1);
        const int grp = tid >> 6;               // 0..7
        const float* gp = (const float*)g_part4;
        float ps = 0.f;
        for (int j = grp; j < ch; j += 8)
            ps += gp[(b * NCHUNK + j) * C_ + c];
        pred[grp][c] = ps;
    }

    // Register inclusive scan of the 4 rows.
    v1.x += v0.x; v1.y += v0.y; v1.z += v0.z; v1.w += v0.w;
    v2.x += v1.x; v2.y += v1.y; v2.z += v1.z; v2.w += v1.w;
    v3.x += v2.x; v3.y += v2.y; v3.z += v2.z; v3.w += v2.w;

    red[rl][cg] = v3;
    __syncthreads();

    // Combine the 8 predecessor groups.
    if (tid < C_)
        predt[tid] = ((pred[0][tid] + pred[1][tid]) + (pred[2][tid] + pred[3][tid]))
                   + ((pred[4][tid] + pred[5][tid]) + (pred[6][tid] + pred[7][tid]));

    // Exclusive base across lower row lanes (<=31 shared loads, independent).
    float4 base = make_float4(0.f, 0.f, 0.f, 0.f);
    for (int r = 0; r < rl; r++) {
        float4 t4 = red[r][cg];
        base.x += t4.x; base.y += t4.y; base.z += t4.z; base.w += t4.w;
    }
    __syncthreads();

    {
        float4 pb = ((const float4*)predt)[cg];
        base.x += pb.x; base.y += pb.y; base.z += pb.z; base.w += pb.w;
    }

    const float* rp = &s_recip[rl * RPT2];
    float4* __restrict__ yp = (float4*)(y + off);
    float4 o;
    #define EMIT(K, VK)                                        \
        { float r = rp[K];                                     \
          o.x = (VK.x + base.x) * r; o.y = (VK.y + base.y) * r;\
          o.z = (VK.z + base.z) * r; o.w = (VK.w + base.w) * r;\
          yp[K * (C_ / 4)] = o; }
    EMIT(0, v0) EMIT(1, v1) EMIT(2, v2) EMIT(3, v3)
    #undef EMIT
}

extern "C" void kernel_launch(void* const* d_in, const int* in_sizes, int n_in,
                              void* d_out, int out_size) {
    (void)in_sizes; (void)n_in; (void)out_size;
    const float* x = (const float*)d_in[0];   // [16, 8192, 64] fp32
    // d_in[1] (weights) is mathematically the causal 1/(i+1) matrix -> never read.
    float* y = (float*)d_out;

    k_partial<<<NBLK, NTHR1>>>(x);
    k_scanout<<<NBLK, NTHR2>>>(x, y);
}

// round 14
// speedup vs baseline: 1.5673x; 1.5673x over previous
#include <cuda_runtime.h>

// y[b,t,c] = (1/(t+1)) * sum_{j<=t} x[b,j,c]   (cumulative mean along T)
// Two-pass, serialization-free:
//   K1: per-(b, 128-row chunk) channel sums -> g_part
//   K2: local register scan + predecessor-partial sum + scaled store
// R9 lesson: RL=32 blew up the serial exclusive-base loop (L1 42%). Revert to
// R6 shape (256 thr, RPT=8, RL=16) and instead kill the wave tail: each K2 CTA
// handles TWO adjacent chunks sequentially -> 512 CTAs = single wave.
// (R10 was an infra failure; this is the same kernel resubmitted.)

#define B_      16
#define T_      8192
#define C_      64
#define CHUNK   128
#define NCHUNK  (T_ / CHUNK)          // 64
#define NPAIR   (NCHUNK / 2)          // 32
#define NBLK1   (B_ * NCHUNK)         // 1024 (K1)
#define NBLK2   (B_ * NPAIR)          // 512  (K2) -> single wave
#define NTHR    256
#define CG      16                    // float4 channel groups
#define RL      (NTHR / CG)           // 16 row lanes
#define RPT     (CHUNK / RL)          // 8 rows per thread

// Per-chunk channel sums: [b][chunk][c], float4-aligned. 256 KB.
__device__ float4 g_part4[B_ * NCHUNK * CG];

__global__ void __launch_bounds__(NTHR, 8)
k_partial(const float* __restrict__ x) {
    const int bid = blockIdx.x;
    const int b   = bid >> 6;           // /NCHUNK
    const int ch  = bid & (NCHUNK - 1);
    const int tid = threadIdx.x;
    const int cg  = tid & (CG - 1);
    const int rl  = tid >> 4;

    const int row0 = ch * CHUNK + rl * RPT;
    const float4* __restrict__ xp =
        (const float4*)(x + ((size_t)(b * T_ + row0)) * C_ + cg * 4);

    float4 s = make_float4(0.f, 0.f, 0.f, 0.f);
    #pragma unroll
    for (int k = 0; k < RPT; k++) {
        float4 v = xp[k * (C_ / 4)];
        s.x += v.x; s.y += v.y; s.z += v.z; s.w += v.w;
    }

    __shared__ float4 red1[RL][CG];
    red1[rl][cg] = s;
    #pragma unroll
    for (int st = RL / 2; st > 0; st >>= 1) {
        __syncthreads();
        if (rl < st) {
            float4 o = red1[rl + st][cg];
            float4 m = red1[rl][cg];
            m.x += o.x; m.y += o.y; m.z += o.z; m.w += o.w;
            red1[rl][cg] = m;
        }
    }
    __syncthreads();
    if (rl == 0)
        g_part4[(b * NCHUNK + ch) * CG + cg] = red1[0][cg];
}

// min-blocks=3 -> ~62 regs: the 8x float4 tile stays register-resident.
__global__ void __launch_bounds__(NTHR, 3)
k_scanout(const float* __restrict__ x, float* __restrict__ y) {
    const int bid = blockIdx.x;
    const int b   = bid >> 5;           // /NPAIR
    const int pr  = bid & (NPAIR - 1);
    const int ch0 = pr * 2;             // phase A chunk
    const int tid = threadIdx.x;
    const int cg  = tid & (CG - 1);
    const int rl  = tid >> 4;           // 0..15

    __shared__ float4 red[RL][CG];
    __shared__ float  pred[4][C_];
    __shared__ float  predt[C_];        // sum of partials for chunks < ch0
    __shared__ float  s_totA[C_];       // phase A tile total
    __shared__ float  s_recip[2 * CHUNK];

    // Reciprocal table for both chunks' global rows (full-precision divide).
    s_recip[tid] = 1.0f / (float)(ch0 * CHUNK + tid + 1);

    // Predecessor chunk partials (< ch0): 4 groups x 64 channels, L2-hot.
    {
        const int c   = tid & (C_ - 1);
        const int grp = tid >> 6;               // 0..3
        const float* gp = (const float*)g_part4;
        float ps = 0.f;
        for (int j = grp; j < ch0; j += 4)
            ps += gp[(b * NCHUNK + j) * C_ + c];
        pred[grp][c] = ps;
    }

    // ================= Phase A: chunk ch0 =================
    const int rowA = ch0 * CHUNK + rl * RPT;
    const size_t offA = ((size_t)(b * T_ + rowA)) * C_ + cg * 4;
    {
        const float4* __restrict__ xp = (const float4*)(x + offA);
        float4 v0 = xp[0 * (C_ / 4)];
        float4 v1 = xp[1 * (C_ / 4)];
        float4 v2 = xp[2 * (C_ / 4)];
        float4 v3 = xp[3 * (C_ / 4)];
        float4 v4 = xp[4 * (C_ / 4)];
        float4 v5 = xp[5 * (C_ / 4)];
        float4 v6 = xp[6 * (C_ / 4)];
        float4 v7 = xp[7 * (C_ / 4)];

        v1.x += v0.x; v1.y += v0.y; v1.z += v0.z; v1.w += v0.w;
        v2.x += v1.x; v2.y += v1.y; v2.z += v1.z; v2.w += v1.w;
        v3.x += v2.x; v3.y += v2.y; v3.z += v2.z; v3.w += v2.w;
        v4.x += v3.x; v4.y += v3.y; v4.z += v3.z; v4.w += v3.w;
        v5.x += v4.x; v5.y += v4.y; v5.z += v4.z; v5.w += v4.w;
        v6.x += v5.x; v6.y += v5.y; v6.z += v5.z; v6.w += v5.w;
        v7.x += v6.x; v7.y += v6.y; v7.z += v6.z; v7.w += v6.w;

        red[rl][cg] = v7;
        __syncthreads();

        // Combine the 4 predecessor groups (once).
        if (tid < C_)
            predt[tid] = (pred[0][tid] + pred[1][tid])
                       + (pred[2][tid] + pred[3][tid]);

        // Exclusive base across lower row lanes (<=15 shared loads).
        float4 base = make_float4(0.f, 0.f, 0.f, 0.f);
        for (int r = 0; r < rl; r++) {
            float4 t4 = red[r][cg];
            base.x += t4.x; base.y += t4.y; base.z += t4.z; base.w += t4.w;
        }

        // Top lane publishes phase A total for phase B.
        if (rl == RL - 1) {
            float4 tot;
            tot.x = base.x + v7.x; tot.y = base.y + v7.y;
            tot.z = base.z + v7.z; tot.w = base.w + v7.w;
            ((float4*)s_totA)[cg] = tot;
        }
        __syncthreads();   // predt/s_totA ready; all red reads done

        {
            float4 pb = ((const float4*)predt)[cg];
            base.x += pb.x; base.y += pb.y; base.z += pb.z; base.w += pb.w;
        }

        const float* rp = &s_recip[rl * RPT];
        float4* __restrict__ yp = (float4*)(y + offA);
        float4 o;
        #define EMIT(K, VK)                                        \
            { float r = rp[K];                                     \
              o.x = (VK.x + base.x) * r; o.y = (VK.y + base.y) * r;\
              o.z = (VK.z + base.z) * r; o.w = (VK.w + base.w) * r;\
              yp[K * (C_ / 4)] = o; }
        EMIT(0, v0) EMIT(1, v1) EMIT(2, v2) EMIT(3, v3)
        EMIT(4, v4) EMIT(5, v5) EMIT(6, v6) EMIT(7, v7)
        #undef EMIT
    }

    // ================= Phase B: chunk ch0+1 =================
    const size_t offB = offA + (size_t)CHUNK * C_;
    {
        const float4* __restrict__ xp = (const float4*)(x + offB);
        float4 v0 = xp[0 * (C_ / 4)];
        float4 v1 = xp[1 * (C_ / 4)];
        float4 v2 = xp[2 * (C_ / 4)];
        float4 v3 = xp[3 * (C_ / 4)];
        float4 v4 = xp[4 * (C_ / 4)];
        float4 v5 = xp[5 * (C_ / 4)];
        float4 v6 = xp[6 * (C_ / 4)];
        float4 v7 = xp[7 * (C_ / 4)];

        v1.x += v0.x; v1.y += v0.y; v1.z += v0.z; v1.w += v0.w;
        v2.x += v1.x; v2.y += v1.y; v2.z += v1.z; v2.w += v1.w;
        v3.x += v2.x; v3.y += v2.y; v3.z += v2.z; v3.w += v2.w;
        v4.x += v3.x; v4.y += v3.y; v4.z += v3.z; v4.w += v3.w;
        v5.x += v4.x; v5.y += v4.y; v5.z += v4.z; v5.w += v4.w;
        v6.x += v5.x; v6.y += v5.y; v6.z += v5.z; v6.w += v5.w;
        v7.x += v6.x; v7.y += v6.y; v7.z += v6.z; v7.w += v6.w;

        red[rl][cg] = v7;   // safe: all phase A reads of red completed pre-sync
        __syncthreads();

        float4 base = make_float4(0.f, 0.f, 0.f, 0.f);
        for (int r = 0; r < rl; r++) {
            float4 t4 = red[r][cg];
            base.x += t4.x; base.y += t4.y; base.z += t4.z; base.w += t4.w;
        }

        {
            float4 pb = ((const float4*)predt)[cg];
            float4 ta = ((const float4*)s_totA)[cg];
            base.x += pb.x + ta.x; base.y += pb.y + ta.y;
            base.z += pb.z + ta.z; base.w += pb.w + ta.w;
        }

        const float* rp = &s_recip[CHUNK + rl * RPT];
        float4* __restrict__ yp = (float4*)(y + offB);
        float4 o;
        #define EMIT(K, VK)                                        \
            { float r = rp[K];                                     \
              o.x = (VK.x + base.x) * r; o.y = (VK.y + base.y) * r;\
              o.z = (VK.z + base.z) * r; o.w = (VK.w + base.w) * r;\
              yp[K * (C_ / 4)] = o; }
        EMIT(0, v0) EMIT(1, v1) EMIT(2, v2) EMIT(3, v3)
        EMIT(4, v4) EMIT(5, v5) EMIT(6, v6) EMIT(7, v7)
        #undef EMIT
    }
}

extern "C" void kernel_launch(void* const* d_in, const int* in_sizes, int n_in,
                              void* d_out, int out_size) {
    (void)in_sizes; (void)n_in; (void)out_size;
    const float* x = (const float*)d_in[0];   // [16, 8192, 64] fp32
    // d_in[1] (weights) is mathematically the causal 1/(i+1) matrix -> never read.
    float* y = (float*)d_out;

    k_partial<<<NBLK1, NTHR>>>(x);
    k_scanout<<<NBLK2, NTHR>>>(x, y);
}